// round 1
// baseline (speedup 1.0000x reference)
#include <cuda_runtime.h>
#include <math.h>

// Problem constants
constexpr int kH = 2048;   // hidden
constexpr int kI = 1024;   // intermediate
constexpr int kE = 16;     // experts
constexpr int kTopK = 8;
constexpr int kR = 602;    // lora rank
constexpr int kT = 8192;   // tokens (4*2048)

// ---------------- scratch (device globals; no allocation allowed) -----------
__device__ float g_base_g[kT * kI];
__device__ float g_base_u[kT * kI];
__device__ float g_tg[kT * kR];
__device__ float g_tu[kT * kR];
__device__ float g_gbuf[kT * kI];   // g, then h in-place
__device__ float g_ubuf[kT * kI];
__device__ float g_td[kT * kR];
__device__ float g_combine[kT * kE];
__device__ int   g_lists[kE * kT];
__device__ int   g_counts[kE];

// ---------------- init: zero out accumulator + counts -----------------------
__global__ void init_kernel(float* __restrict__ out) {
    long idx = (long)blockIdx.x * blockDim.x + threadIdx.x;
    long stride = (long)gridDim.x * blockDim.x;
    long total = (long)kT * kH;
    for (long i = idx; i < total; i += stride) out[i] = 0.0f;
    if (idx < kE) g_counts[idx] = 0;
}

// ---------------- router: logits, softmax, top-8, lists ---------------------
__global__ void router_kernel(const float* __restrict__ x,
                              const float* __restrict__ wr,
                              float* __restrict__ logits_out) {
    int t = blockIdx.x;
    __shared__ float xs[kH];
    __shared__ float lg[kE];
    int tid = threadIdx.x;
    for (int i = tid; i < kH; i += 256) xs[i] = x[(long)t * kH + i];
    __syncthreads();

    int w = tid >> 5, lane = tid & 31;
    #pragma unroll
    for (int eo = 0; eo < 2; eo++) {
        int e = w * 2 + eo;
        const float* wre = wr + (long)e * kH;
        float s = 0.0f;
        for (int i = lane; i < kH; i += 32) s += xs[i] * wre[i];
        #pragma unroll
        for (int o = 16; o; o >>= 1) s += __shfl_xor_sync(0xffffffff, s, o);
        if (lane == 0) lg[e] = s;
    }
    __syncthreads();

    if (tid == 0) {
        float mx = lg[0];
        for (int e = 1; e < kE; e++) mx = fmaxf(mx, lg[e]);
        float p[kE]; float sum = 0.0f;
        for (int e = 0; e < kE; e++) { p[e] = expf(lg[e] - mx); sum += p[e]; }
        float inv = 1.0f / sum;
        for (int e = 0; e < kE; e++) p[e] *= inv;
        bool used[kE];
        for (int e = 0; e < kE; e++) used[e] = false;
        int sel[kTopK]; float tsum = 0.0f;
        for (int k = 0; k < kTopK; k++) {
            int bi = -1; float bv = -1.0f;
            for (int e = 0; e < kE; e++)
                if (!used[e] && p[e] > bv) { bv = p[e]; bi = e; }
            used[bi] = true; sel[k] = bi; tsum += bv;
        }
        float itn = 1.0f / tsum;
        for (int e = 0; e < kE; e++)
            g_combine[t * kE + e] = used[e] ? p[e] * itn : 0.0f;
        for (int k = 0; k < kTopK; k++) {
            int e = sel[k];
            int pos = atomicAdd(&g_counts[e], 1);
            g_lists[e * kT + pos] = t;
        }
    }
    if (tid < kE) logits_out[t * kE + tid] = lg[tid];
}

// ---------------- generic tiled SGEMM: C(+)= A @ B^T -------------------------
// A: [M, lda]  (rows possibly gathered via list)
// B: [nB, ldb] (rows >= nB treated as zero), K columns used
// mode 0: C[r*ldc+c] = acc
// mode 1: C[r*ldc+c] = base[tok*ldbase+c] + acc   (tok = list[r])
// mode 2: C[tok*ldc+c] += combine[tok*kE+expert] * acc
#define BM 128
#define BN 128
#define BK 16

__global__ __launch_bounds__(256) void gemm_kernel(
    const float* __restrict__ A, int lda,
    const float* __restrict__ B, int ldb, int nB, int K,
    float* __restrict__ C, int ldc, int N,
    int M_static, const int* __restrict__ countPtr,
    const int* __restrict__ list, int gatherA,
    const float* __restrict__ base, int ldbase,
    const float* __restrict__ combine, int expert,
    int mode)
{
    int M = countPtr ? *countPtr : M_static;
    int row0 = blockIdx.y * BM;
    if (row0 >= M) return;
    int col0 = blockIdx.x * BN;

    __shared__ float As[BK][BM + 4];
    __shared__ float Bs[BK][BN + 4];
    __shared__ int arow[BM];
    __shared__ int tokS[BM];

    int tid = threadIdx.x;
    for (int i = tid; i < BM; i += 256) {
        int r = row0 + i;
        int tk = (r < M && list) ? list[r] : r;
        tokS[i] = tk;
        arow[i] = (r < M) ? (gatherA ? tk : r) : -1;
    }
    __syncthreads();

    float acc[8][8];
    #pragma unroll
    for (int i = 0; i < 8; i++)
        #pragma unroll
        for (int j = 0; j < 8; j++) acc[i][j] = 0.0f;

    int tx = tid & 15, ty = tid >> 4;
    int kTiles = (K + BK - 1) / BK;

    for (int kt = 0; kt < kTiles; kt++) {
        int kb = kt * BK;
        // A tile: 128 rows x 16 k
        #pragma unroll
        for (int it = 0; it < 8; it++) {
            int r = (tid >> 4) + it * 16;
            int c = tid & 15;
            int gk = kb + c;
            int ar = arow[r];
            float v = (ar >= 0 && gk < K) ? A[(long)ar * lda + gk] : 0.0f;
            As[c][r] = v;
        }
        // B tile: 128 n-rows x 16 k
        #pragma unroll
        for (int it = 0; it < 8; it++) {
            int r = (tid >> 4) + it * 16;
            int c = tid & 15;
            int gn = col0 + r;
            int gk = kb + c;
            float v = (gn < nB && gk < K) ? B[(long)gn * ldb + gk] : 0.0f;
            Bs[c][r] = v;
        }
        __syncthreads();

        #pragma unroll
        for (int kk = 0; kk < BK; kk++) {
            float a[8], b[8];
            #pragma unroll
            for (int i = 0; i < 8; i++) a[i] = As[kk][ty * 8 + i];
            #pragma unroll
            for (int j = 0; j < 8; j++) b[j] = Bs[kk][tx * 8 + j];
            #pragma unroll
            for (int i = 0; i < 8; i++)
                #pragma unroll
                for (int j = 0; j < 8; j++)
                    acc[i][j] = fmaf(a[i], b[j], acc[i][j]);
        }
        __syncthreads();
    }

    // epilogue
    #pragma unroll
    for (int i = 0; i < 8; i++) {
        int li = ty * 8 + i;
        int r = row0 + li;
        if (r >= M) continue;
        int tk = tokS[li];
        float w = 0.0f;
        if (mode == 2) w = combine[tk * kE + expert];
        #pragma unroll
        for (int j = 0; j < 8; j++) {
            int c = col0 + tx * 8 + j;
            if (c >= N) continue;
            if (mode == 0) {
                C[(long)r * ldc + c] = acc[i][j];
            } else if (mode == 1) {
                C[(long)r * ldc + c] = base[(long)tk * ldbase + c] + acc[i][j];
            } else {
                C[(long)tk * ldc + c] += w * acc[i][j];
            }
        }
    }
}

// ---------------- h = silu(g) * u (in place into g) -------------------------
__global__ void silu_mul_kernel(const float* __restrict__ g,
                                const float* __restrict__ u,
                                float* __restrict__ h,
                                const int* __restrict__ countPtr) {
    int M = *countPtr;
    long total = (long)M * kI;
    long idx = (long)blockIdx.x * blockDim.x + threadIdx.x;
    long stride = (long)gridDim.x * blockDim.x;
    for (long i = idx; i < total; i += stride) {
        float gv = g[i], uv = u[i];
        h[i] = (gv / (1.0f + expf(-gv))) * uv;
    }
}

// ---------------- launch --------------------------------------------------
extern "C" void kernel_launch(void* const* d_in, const int* in_sizes, int n_in,
                              void* d_out, int out_size) {
    const float* x  = (const float*)d_in[0];
    const float* wr = (const float*)d_in[1];
    const float* Wg = (const float*)d_in[2];
    const float* Wu = (const float*)d_in[3];
    const float* Wd = (const float*)d_in[4];
    const float* Ag = (const float*)d_in[5];
    const float* Bg = (const float*)d_in[6];
    const float* Au = (const float*)d_in[7];
    const float* Bu = (const float*)d_in[8];
    const float* Ad = (const float*)d_in[9];
    const float* Bd = (const float*)d_in[10];

    float* out = (float*)d_out;
    float* logits_out = out + (long)kT * kH;

    void *p;
    cudaGetSymbolAddress(&p, g_base_g);  float* base_g = (float*)p;
    cudaGetSymbolAddress(&p, g_base_u);  float* base_u = (float*)p;
    cudaGetSymbolAddress(&p, g_tg);      float* tg = (float*)p;
    cudaGetSymbolAddress(&p, g_tu);      float* tu = (float*)p;
    cudaGetSymbolAddress(&p, g_gbuf);    float* gb = (float*)p;
    cudaGetSymbolAddress(&p, g_ubuf);    float* ub = (float*)p;
    cudaGetSymbolAddress(&p, g_td);      float* td = (float*)p;
    cudaGetSymbolAddress(&p, g_combine); float* combine = (float*)p;
    cudaGetSymbolAddress(&p, g_lists);   int* lists = (int*)p;
    cudaGetSymbolAddress(&p, g_counts);  int* counts = (int*)p;

    init_kernel<<<4096, 256>>>(out);
    router_kernel<<<kT, 256>>>(x, wr, logits_out);

    // shared base projections: base_g = x @ Wg^T, base_u = x @ Wu^T
    gemm_kernel<<<dim3(8, 64), 256>>>(x, kH, Wg, kH, kI, kH,
                                      base_g, kI, kI,
                                      kT, nullptr, nullptr, 0,
                                      nullptr, 0, nullptr, 0, 0);
    gemm_kernel<<<dim3(8, 64), 256>>>(x, kH, Wu, kH, kI, kH,
                                      base_u, kI, kI,
                                      kT, nullptr, nullptr, 0,
                                      nullptr, 0, nullptr, 0, 0);

    const int gridR = (kR + BN - 1) / BN;   // 5
    const int gridI = kI / BN;              // 8
    const int gridH = kH / BN;              // 16

    for (int e = 0; e < kE; e++) {
        const float* Ag_e = Ag + (long)e * kR * kH;
        const float* Bg_e = Bg + (long)e * kI * kR;
        const float* Au_e = Au + (long)e * kR * kH;
        const float* Bu_e = Bu + (long)e * kI * kR;
        const float* Ad_e = Ad + (long)e * kR * kI;
        const float* Bd_e = Bd + (long)e * kH * kR;
        const int* cnt = counts + e;
        const int* lst = lists + (long)e * kT;

        // tg = gather(x) @ Ag_e^T    [n_e, R]
        gemm_kernel<<<dim3(gridR, 64), 256>>>(x, kH, Ag_e, kH, kR, kH,
                                              tg, kR, kR,
                                              kT, cnt, lst, 1,
                                              nullptr, 0, nullptr, 0, 0);
        // tu = gather(x) @ Au_e^T
        gemm_kernel<<<dim3(gridR, 64), 256>>>(x, kH, Au_e, kH, kR, kH,
                                              tu, kR, kR,
                                              kT, cnt, lst, 1,
                                              nullptr, 0, nullptr, 0, 0);
        // g = base_g[tok] + tg @ Bg_e^T    [n_e, I]
        gemm_kernel<<<dim3(gridI, 64), 256>>>(tg, kR, Bg_e, kR, kI, kR,
                                              gb, kI, kI,
                                              kT, cnt, lst, 0,
                                              base_g, kI, nullptr, 0, 1);
        // u = base_u[tok] + tu @ Bu_e^T
        gemm_kernel<<<dim3(gridI, 64), 256>>>(tu, kR, Bu_e, kR, kI, kR,
                                              ub, kI, kI,
                                              kT, cnt, lst, 0,
                                              base_u, kI, nullptr, 0, 1);
        // h = silu(g) * u  (in place into gb)
        silu_mul_kernel<<<8192, 256>>>(gb, ub, gb, cnt);
        // td = h @ Ad_e^T   [n_e, R]
        gemm_kernel<<<dim3(gridR, 64), 256>>>(gb, kI, Ad_e, kI, kR, kI,
                                              td, kR, kR,
                                              kT, cnt, nullptr, 0,
                                              nullptr, 0, nullptr, 0, 0);
        // out[tok] += c * (h @ Wd^T)
        gemm_kernel<<<dim3(gridH, 64), 256>>>(gb, kI, Wd, kI, kH, kI,
                                              out, kH, kH,
                                              kT, cnt, lst, 0,
                                              nullptr, 0, combine, e, 2);
        // out[tok] += c * (td @ Bd_e^T)
        gemm_kernel<<<dim3(gridH, 64), 256>>>(td, kR, Bd_e, kR, kH, kR,
                                              out, kH, kH,
                                              kT, cnt, lst, 0,
                                              nullptr, 0, combine, e, 2);
    }

    (void)in_sizes; (void)n_in; (void)out_size;
}

// round 2
// speedup vs baseline: 1.0146x; 1.0146x over previous
#include <cuda_runtime.h>
#include <math.h>

// Problem constants
constexpr int kH = 2048;   // hidden
constexpr int kI = 1024;   // intermediate
constexpr int kE = 16;     // experts
constexpr int kTopK = 8;
constexpr int kR = 602;    // lora rank
constexpr int kT = 8192;   // tokens (4*2048)

// ---------------- scratch (device globals; no allocation allowed) -----------
__device__ float g_base_g[kT * kI];
__device__ float g_base_u[kT * kI];
__device__ float g_tg[kT * kR];
__device__ float g_tu[kT * kR];
__device__ float g_gbuf[kT * kI];   // g, then h in-place
__device__ float g_ubuf[kT * kI];
__device__ float g_td[kT * kR];
__device__ float g_combine[kT * kE];
__device__ int   g_lists[kE * kT];
__device__ int   g_counts[kE];

// ---------------- init: zero out accumulator + counts -----------------------
__global__ void init_kernel(float* __restrict__ out) {
    long idx = (long)blockIdx.x * blockDim.x + threadIdx.x;
    long stride = (long)gridDim.x * blockDim.x;
    long total = (long)kT * kH;
    for (long i = idx; i < total; i += stride) out[i] = 0.0f;
    if (idx < kE) g_counts[idx] = 0;
}

// ---------------- router: logits, softmax, top-8, lists ---------------------
__global__ void router_kernel(const float* __restrict__ x,
                              const float* __restrict__ wr,
                              float* __restrict__ logits_out) {
    int t = blockIdx.x;
    __shared__ float xs[kH];
    __shared__ float lg[kE];
    int tid = threadIdx.x;
    for (int i = tid; i < kH; i += 256) xs[i] = x[(long)t * kH + i];
    __syncthreads();

    int w = tid >> 5, lane = tid & 31;
    #pragma unroll
    for (int eo = 0; eo < 2; eo++) {
        int e = w * 2 + eo;
        const float* wre = wr + (long)e * kH;
        float s = 0.0f;
        for (int i = lane; i < kH; i += 32) s += xs[i] * wre[i];
        #pragma unroll
        for (int o = 16; o; o >>= 1) s += __shfl_xor_sync(0xffffffff, s, o);
        if (lane == 0) lg[e] = s;
    }
    __syncthreads();

    if (tid == 0) {
        float mx = lg[0];
        for (int e = 1; e < kE; e++) mx = fmaxf(mx, lg[e]);
        float p[kE]; float sum = 0.0f;
        for (int e = 0; e < kE; e++) { p[e] = expf(lg[e] - mx); sum += p[e]; }
        float inv = 1.0f / sum;
        for (int e = 0; e < kE; e++) p[e] *= inv;
        bool used[kE];
        for (int e = 0; e < kE; e++) used[e] = false;
        int sel[kTopK]; float tsum = 0.0f;
        for (int k = 0; k < kTopK; k++) {
            int bi = -1; float bv = -1.0f;
            for (int e = 0; e < kE; e++)
                if (!used[e] && p[e] > bv) { bv = p[e]; bi = e; }
            used[bi] = true; sel[k] = bi; tsum += bv;
        }
        float itn = 1.0f / tsum;
        for (int e = 0; e < kE; e++)
            g_combine[t * kE + e] = used[e] ? p[e] * itn : 0.0f;
        for (int k = 0; k < kTopK; k++) {
            int e = sel[k];
            int pos = atomicAdd(&g_counts[e], 1);
            g_lists[e * kT + pos] = t;
        }
    }
    if (tid < kE) logits_out[t * kE + tid] = lg[tid];
}

// ---------------- generic tiled SGEMM: C(+)= A @ B^T -------------------------
// A: [M, lda]  (rows possibly gathered via list)
// B: [nB, ldb] (rows >= nB treated as zero), K columns used
// mode 0: C[r*ldc+c] = acc
// mode 1: C[r*ldc+c] = base[tok*ldbase+c] + acc   (tok = list[r])
// mode 2: C[tok*ldc+c] += combine[tok*kE+expert] * acc
#define BM 128
#define BN 128
#define BK 16

__global__ __launch_bounds__(256) void gemm_kernel(
    const float* __restrict__ A, int lda,
    const float* __restrict__ B, int ldb, int nB, int K,
    float* __restrict__ C, int ldc, int N,
    int M_static, const int* __restrict__ countPtr,
    const int* __restrict__ list, int gatherA,
    const float* __restrict__ base, int ldbase,
    const float* __restrict__ combine, int expert,
    int mode)
{
    int M = countPtr ? *countPtr : M_static;
    int row0 = blockIdx.y * BM;
    if (row0 >= M) return;
    int col0 = blockIdx.x * BN;

    __shared__ float As[BK][BM + 4];
    __shared__ float Bs[BK][BN + 4];
    __shared__ int arow[BM];
    __shared__ int tokS[BM];

    int tid = threadIdx.x;
    for (int i = tid; i < BM; i += 256) {
        int r = row0 + i;
        int tk = (r < M && list) ? list[r] : r;
        tokS[i] = tk;
        arow[i] = (r < M) ? (gatherA ? tk : r) : -1;
    }
    __syncthreads();

    float acc[8][8];
    #pragma unroll
    for (int i = 0; i < 8; i++)
        #pragma unroll
        for (int j = 0; j < 8; j++) acc[i][j] = 0.0f;

    int tx = tid & 15, ty = tid >> 4;
    int kTiles = (K + BK - 1) / BK;

    for (int kt = 0; kt < kTiles; kt++) {
        int kb = kt * BK;
        // A tile: 128 rows x 16 k
        #pragma unroll
        for (int it = 0; it < 8; it++) {
            int r = (tid >> 4) + it * 16;
            int c = tid & 15;
            int gk = kb + c;
            int ar = arow[r];
            float v = (ar >= 0 && gk < K) ? A[(long)ar * lda + gk] : 0.0f;
            As[c][r] = v;
        }
        // B tile: 128 n-rows x 16 k
        #pragma unroll
        for (int it = 0; it < 8; it++) {
            int r = (tid >> 4) + it * 16;
            int c = tid & 15;
            int gn = col0 + r;
            int gk = kb + c;
            float v = (gn < nB && gk < K) ? B[(long)gn * ldb + gk] : 0.0f;
            Bs[c][r] = v;
        }
        __syncthreads();

        #pragma unroll
        for (int kk = 0; kk < BK; kk++) {
            float a[8], b[8];
            #pragma unroll
            for (int i = 0; i < 8; i++) a[i] = As[kk][ty * 8 + i];
            #pragma unroll
            for (int j = 0; j < 8; j++) b[j] = Bs[kk][tx * 8 + j];
            #pragma unroll
            for (int i = 0; i < 8; i++)
                #pragma unroll
                for (int j = 0; j < 8; j++)
                    acc[i][j] = fmaf(a[i], b[j], acc[i][j]);
        }
        __syncthreads();
    }

    // epilogue
    #pragma unroll
    for (int i = 0; i < 8; i++) {
        int li = ty * 8 + i;
        int r = row0 + li;
        if (r >= M) continue;
        int tk = tokS[li];
        float w = 0.0f;
        if (mode == 2) w = combine[tk * kE + expert];
        #pragma unroll
        for (int j = 0; j < 8; j++) {
            int c = col0 + tx * 8 + j;
            if (c >= N) continue;
            if (mode == 0) {
                C[(long)r * ldc + c] = acc[i][j];
            } else if (mode == 1) {
                C[(long)r * ldc + c] = base[(long)tk * ldbase + c] + acc[i][j];
            } else {
                C[(long)tk * ldc + c] += w * acc[i][j];
            }
        }
    }
}

// ---------------- h = silu(g) * u (in place into g) -------------------------
__global__ void silu_mul_kernel(const float* __restrict__ g,
                                const float* __restrict__ u,
                                float* __restrict__ h,
                                const int* __restrict__ countPtr) {
    int M = *countPtr;
    long total = (long)M * kI;
    long idx = (long)blockIdx.x * blockDim.x + threadIdx.x;
    long stride = (long)gridDim.x * blockDim.x;
    for (long i = idx; i < total; i += stride) {
        float gv = g[i], uv = u[i];
        h[i] = (gv / (1.0f + expf(-gv))) * uv;
    }
}

// ---------------- launch --------------------------------------------------
extern "C" void kernel_launch(void* const* d_in, const int* in_sizes, int n_in,
                              void* d_out, int out_size) {
    const float* x  = (const float*)d_in[0];
    const float* wr = (const float*)d_in[1];
    const float* Wg = (const float*)d_in[2];
    const float* Wu = (const float*)d_in[3];
    const float* Wd = (const float*)d_in[4];
    const float* Ag = (const float*)d_in[5];
    const float* Bg = (const float*)d_in[6];
    const float* Au = (const float*)d_in[7];
    const float* Bu = (const float*)d_in[8];
    const float* Ad = (const float*)d_in[9];
    const float* Bd = (const float*)d_in[10];

    float* out = (float*)d_out;
    float* logits_out = out + (long)kT * kH;

    void *p;
    cudaGetSymbolAddress(&p, g_base_g);  float* base_g = (float*)p;
    cudaGetSymbolAddress(&p, g_base_u);  float* base_u = (float*)p;
    cudaGetSymbolAddress(&p, g_tg);      float* tg = (float*)p;
    cudaGetSymbolAddress(&p, g_tu);      float* tu = (float*)p;
    cudaGetSymbolAddress(&p, g_gbuf);    float* gb = (float*)p;
    cudaGetSymbolAddress(&p, g_ubuf);    float* ub = (float*)p;
    cudaGetSymbolAddress(&p, g_td);      float* td = (float*)p;
    cudaGetSymbolAddress(&p, g_combine); float* combine = (float*)p;
    cudaGetSymbolAddress(&p, g_lists);   int* lists = (int*)p;
    cudaGetSymbolAddress(&p, g_counts);  int* counts = (int*)p;

    init_kernel<<<4096, 256>>>(out);
    router_kernel<<<kT, 256>>>(x, wr, logits_out);

    // shared base projections: base_g = x @ Wg^T, base_u = x @ Wu^T
    gemm_kernel<<<dim3(8, 64), 256>>>(x, kH, Wg, kH, kI, kH,
                                      base_g, kI, kI,
                                      kT, nullptr, nullptr, 0,
                                      nullptr, 0, nullptr, 0, 0);
    gemm_kernel<<<dim3(8, 64), 256>>>(x, kH, Wu, kH, kI, kH,
                                      base_u, kI, kI,
                                      kT, nullptr, nullptr, 0,
                                      nullptr, 0, nullptr, 0, 0);

    const int gridR = (kR + BN - 1) / BN;   // 5
    const int gridI = kI / BN;              // 8
    const int gridH = kH / BN;              // 16

    for (int e = 0; e < kE; e++) {
        const float* Ag_e = Ag + (long)e * kR * kH;
        const float* Bg_e = Bg + (long)e * kI * kR;
        const float* Au_e = Au + (long)e * kR * kH;
        const float* Bu_e = Bu + (long)e * kI * kR;
        const float* Ad_e = Ad + (long)e * kR * kI;
        const float* Bd_e = Bd + (long)e * kH * kR;
        const int* cnt = counts + e;
        const int* lst = lists + (long)e * kT;

        // tg = gather(x) @ Ag_e^T    [n_e, R]
        gemm_kernel<<<dim3(gridR, 64), 256>>>(x, kH, Ag_e, kH, kR, kH,
                                              tg, kR, kR,
                                              kT, cnt, lst, 1,
                                              nullptr, 0, nullptr, 0, 0);
        // tu = gather(x) @ Au_e^T
        gemm_kernel<<<dim3(gridR, 64), 256>>>(x, kH, Au_e, kH, kR, kH,
                                              tu, kR, kR,
                                              kT, cnt, lst, 1,
                                              nullptr, 0, nullptr, 0, 0);
        // g = base_g[tok] + tg @ Bg_e^T    [n_e, I]
        gemm_kernel<<<dim3(gridI, 64), 256>>>(tg, kR, Bg_e, kR, kI, kR,
                                              gb, kI, kI,
                                              kT, cnt, lst, 0,
                                              base_g, kI, nullptr, 0, 1);
        // u = base_u[tok] + tu @ Bu_e^T
        gemm_kernel<<<dim3(gridI, 64), 256>>>(tu, kR, Bu_e, kR, kI, kR,
                                              ub, kI, kI,
                                              kT, cnt, lst, 0,
                                              base_u, kI, nullptr, 0, 1);
        // h = silu(g) * u  (in place into gb)
        silu_mul_kernel<<<8192, 256>>>(gb, ub, gb, cnt);
        // td = h @ Ad_e^T   [n_e, R]
        gemm_kernel<<<dim3(gridR, 64), 256>>>(gb, kI, Ad_e, kI, kR, kI,
                                              td, kR, kR,
                                              kT, cnt, nullptr, 0,
                                              nullptr, 0, nullptr, 0, 0);
        // out[tok] += c * (h @ Wd^T)
        gemm_kernel<<<dim3(gridH, 64), 256>>>(gb, kI, Wd, kI, kH, kI,
                                              out, kH, kH,
                                              kT, cnt, lst, 0,
                                              nullptr, 0, combine, e, 2);
        // out[tok] += c * (td @ Bd_e^T)
        gemm_kernel<<<dim3(gridH, 64), 256>>>(td, kR, Bd_e, kR, kH, kR,
                                              out, kH, kH,
                                              kT, cnt, lst, 0,
                                              nullptr, 0, combine, e, 2);
    }

    (void)in_sizes; (void)n_in; (void)out_size;
}

// round 4
// speedup vs baseline: 3.3195x; 3.2718x over previous
#include <cuda_runtime.h>
#include <cuda_bf16.h>
#include <cstdint>
#include <math.h>

constexpr int kH = 2048, kI = 1024, kE = 16, kTopK = 8, kR = 602, kT = 8192;
constexpr int kRP = 640;  // rank padded to multiple of 32

// ---------------- device scratch ----------------
__device__ __align__(16) unsigned short d_xs_hi[kT * kH];
__device__ __align__(16) unsigned short d_xs_lo[kT * kH];
__device__ __align__(16) unsigned short d_wg_hi[kI * kH];
__device__ __align__(16) unsigned short d_wg_lo[kI * kH];
__device__ __align__(16) unsigned short d_wu_hi[kI * kH];
__device__ __align__(16) unsigned short d_wu_lo[kI * kH];
__device__ __align__(16) unsigned short d_wd_hi[kH * kI];
__device__ __align__(16) unsigned short d_wd_lo[kH * kI];
__device__ __align__(16) unsigned short d_ag_hi[kE * kR * kH];
__device__ __align__(16) unsigned short d_ag_lo[kE * kR * kH];
__device__ __align__(16) unsigned short d_au_hi[kE * kR * kH];
__device__ __align__(16) unsigned short d_au_lo[kE * kR * kH];
__device__ __align__(16) unsigned short d_bg_hi[kE * kI * kRP];
__device__ __align__(16) unsigned short d_bg_lo[kE * kI * kRP];
__device__ __align__(16) unsigned short d_bu_hi[kE * kI * kRP];
__device__ __align__(16) unsigned short d_bu_lo[kE * kI * kRP];
__device__ __align__(16) unsigned short d_ad_hi[kE * kR * kI];
__device__ __align__(16) unsigned short d_ad_lo[kE * kR * kI];
__device__ __align__(16) unsigned short d_bd_hi[kE * kH * kRP];
__device__ __align__(16) unsigned short d_bd_lo[kE * kH * kRP];
__device__ __align__(16) unsigned short d_tg_hi[kT * kRP];
__device__ __align__(16) unsigned short d_tg_lo[kT * kRP];
__device__ __align__(16) unsigned short d_tu_hi[kT * kRP];
__device__ __align__(16) unsigned short d_tu_lo[kT * kRP];
__device__ __align__(16) unsigned short d_td_hi[kT * kRP];
__device__ __align__(16) unsigned short d_td_lo[kT * kRP];
__device__ __align__(16) unsigned short d_h_hi[kT * kI];
__device__ __align__(16) unsigned short d_h_lo[kT * kI];
__device__ float g_base_g[kT * kI];
__device__ float g_base_u[kT * kI];
__device__ float g_gbuf[kT * kI];
__device__ float g_ubuf[kT * kI];
__device__ float g_combine[kT * kE];
__device__ int   g_lists[kE * kT];
__device__ int   g_counts[kE];

// ---------------- helpers ----------------
__device__ __forceinline__ uint32_t smem_u32(const void* p) {
    uint32_t a;
    asm("{ .reg .u64 t; cvta.to.shared.u64 t, %1; cvt.u32.u64 %0, t; }"
        : "=r"(a) : "l"(p));
    return a;
}
__device__ __forceinline__ void split_bf16(float v, unsigned short& h, unsigned short& l) {
    __nv_bfloat16 bh = __float2bfloat16(v);
    float r = v - __bfloat162float(bh);
    __nv_bfloat16 bl = __float2bfloat16(r);
    h = __bfloat16_as_ushort(bh);
    l = __bfloat16_as_ushort(bl);
}

#define LDM4(r, a)                                                            \
    asm volatile("ldmatrix.sync.aligned.m8n8.x4.shared.b16 {%0,%1,%2,%3}, [%4];" \
                 : "=r"((r)[0]), "=r"((r)[1]), "=r"((r)[2]), "=r"((r)[3])     \
                 : "r"(a))

#define MMA(c, a, b0, b1)                                                     \
    asm volatile("mma.sync.aligned.m16n8k16.row.col.f32.bf16.bf16.f32 "       \
                 "{%0,%1,%2,%3},{%4,%5,%6,%7},{%8,%9},{%0,%1,%2,%3};"         \
                 : "+f"((c)[0]), "+f"((c)[1]), "+f"((c)[2]), "+f"((c)[3])     \
                 : "r"((a)[0]), "r"((a)[1]), "r"((a)[2]), "r"((a)[3]),        \
                   "r"(b0), "r"(b1))

__device__ __forceinline__ void cpa16(uint32_t dst, const void* src, int sz) {
    asm volatile("cp.async.ca.shared.global [%0], [%1], 16, %2;"
                 :: "r"(dst), "l"(src), "r"(sz));
}

// ---------------- init ----------------
__global__ void init_kernel(float* __restrict__ out) {
    long idx = (long)blockIdx.x * blockDim.x + threadIdx.x;
    long stride = (long)gridDim.x * blockDim.x;
    long total = (long)kT * kH;
    for (long i = idx; i < total; i += stride) out[i] = 0.0f;
    if (idx < kE) g_counts[idx] = 0;
}

// ---------------- router ----------------
__global__ void router_kernel(const float* __restrict__ x,
                              const float* __restrict__ wr,
                              float* __restrict__ logits_out) {
    int t = blockIdx.x;
    __shared__ float xs[kH];
    __shared__ float lg[kE];
    int tid = threadIdx.x;
    for (int i = tid; i < kH; i += 256) xs[i] = x[(long)t * kH + i];
    __syncthreads();
    int w = tid >> 5, lane = tid & 31;
    #pragma unroll
    for (int eo = 0; eo < 2; eo++) {
        int e = w * 2 + eo;
        const float* wre = wr + (long)e * kH;
        float s = 0.0f;
        for (int i = lane; i < kH; i += 32) s += xs[i] * wre[i];
        #pragma unroll
        for (int o = 16; o; o >>= 1) s += __shfl_xor_sync(0xffffffff, s, o);
        if (lane == 0) lg[e] = s;
    }
    __syncthreads();
    if (tid == 0) {
        float mx = lg[0];
        for (int e = 1; e < kE; e++) mx = fmaxf(mx, lg[e]);
        float p[kE]; float sum = 0.0f;
        for (int e = 0; e < kE; e++) { p[e] = expf(lg[e] - mx); sum += p[e]; }
        float inv = 1.0f / sum;
        for (int e = 0; e < kE; e++) p[e] *= inv;
        bool used[kE];
        for (int e = 0; e < kE; e++) used[e] = false;
        int sel[kTopK]; float tsum = 0.0f;
        for (int k = 0; k < kTopK; k++) {
            int bi = -1; float bv = -1.0f;
            for (int e = 0; e < kE; e++)
                if (!used[e] && p[e] > bv) { bv = p[e]; bi = e; }
            used[bi] = true; sel[k] = bi; tsum += bv;
        }
        float itn = 1.0f / tsum;
        for (int e = 0; e < kE; e++)
            g_combine[t * kE + e] = used[e] ? p[e] * itn : 0.0f;
        for (int k = 0; k < kTopK; k++) {
            int e = sel[k];
            int pos = atomicAdd(&g_counts[e], 1);
            g_lists[e * kT + pos] = t;
        }
    }
    if (tid < kE) logits_out[t * kE + tid] = lg[tid];
}

// ---------------- split fp32 -> bf16 hi/lo (pads cols srcLd..dstLd) ---------
__global__ void split_kernel(const float* __restrict__ src, int srcLd,
                             unsigned short* __restrict__ hi,
                             unsigned short* __restrict__ lo, int dstLd) {
    int col = blockIdx.x * 256 + threadIdx.x;
    long row = blockIdx.y;
    if (col >= dstLd) return;
    float v = (col < srcLd) ? src[row * srcLd + col] : 0.0f;
    unsigned short h, l;
    split_bf16(v, h, l);
    long o = row * dstLd + col;
    hi[o] = h; lo[o] = l;
}

// ---------------- h = silu(g)*u -> bf16 split ----------------
__global__ void silu_split_kernel(const float* __restrict__ g,
                                  const float* __restrict__ u,
                                  unsigned short* __restrict__ hhi,
                                  unsigned short* __restrict__ hlo,
                                  const int* __restrict__ cnt) {
    int M = *cnt;
    long total = (long)M * kI;
    long idx = (long)blockIdx.x * blockDim.x + threadIdx.x;
    long stride = (long)gridDim.x * blockDim.x;
    for (long i = idx; i < total; i += stride) {
        float gv = g[i], uv = u[i];
        float hv = gv / (1.0f + expf(-gv)) * uv;
        unsigned short h, l;
        split_bf16(hv, h, l);
        hhi[i] = h; hlo[i] = l;
    }
}

// ---------------- mma.sync bf16 GEMM: C(+)= A @ B^T, 3-term split ----------
// CTA tile 128x128, K-tile 32, 8 warps (4 m x 2 n), warp tile 32x64.
// mode 0: C[r]=acc ; 1: C[r]=base[tok]+acc ; 2: C[tok]+=w*acc ; 3: split->Chi/Clo
constexpr int STAGE_B = 40960;                 // 4 planes * 128 rows * 80B
constexpr int AHI_O = 0, ALO_O = 10240, BHI_O = 20480, BLO_O = 30720;
constexpr int GSMEM = 1536 + 2 * STAGE_B;      // 83456

__global__ __launch_bounds__(256) void gemm_mma(
    const unsigned short* __restrict__ Ahi, const unsigned short* __restrict__ Alo,
    int lda,
    const unsigned short* __restrict__ Bhi, const unsigned short* __restrict__ Blo,
    int ldb, int nB, int K,
    float* __restrict__ C, int ldc,
    int M_static, const int* __restrict__ countPtr,
    const int* __restrict__ list, int gatherA,
    const float* __restrict__ base, int ldbase,
    const float* __restrict__ combine, int expert,
    unsigned short* __restrict__ Chi, unsigned short* __restrict__ Clo,
    int mode)
{
    int M = countPtr ? *countPtr : M_static;
    int row0 = blockIdx.y * 128;
    if (row0 >= M) return;
    int col0 = blockIdx.x * 128;

    extern __shared__ char sm[];
    int*   arow = (int*)sm;
    int*   tokS = (int*)(sm + 512);
    float* wS   = (float*)(sm + 1024);
    uint32_t stages_u = smem_u32(sm + 1536);

    int tid = threadIdx.x;
    int lane = tid & 31, wid = tid >> 5;
    int wm = wid & 3, wn = wid >> 2;

    for (int i = tid; i < 128; i += 256) {
        int r = row0 + i;
        int rr = (r < M) ? r : (M - 1);
        int tk = list ? list[rr] : rr;
        tokS[i] = tk;
        arow[i] = gatherA ? tk : rr;
        wS[i] = (mode == 2) ? combine[tk * kE + expert] : 0.0f;
    }
    __syncthreads();

    // per-thread load coords: 512 chunks of 16B per plane, 2 per thread
    // ldmatrix per-lane base offsets
    const uint32_t aOff = (uint32_t)((wm * 32 + (lane & 15)) * 80 + (lane >> 4) * 16);
    const uint32_t bOff = (uint32_t)(BHI_O + (wn * 64 + (lane & 15)) * 80 + (lane >> 4) * 16);

    float acc[2][8][4];
    #pragma unroll
    for (int a = 0; a < 2; a++)
        #pragma unroll
        for (int b = 0; b < 8; b++)
            #pragma unroll
            for (int c = 0; c < 4; c++) acc[a][b][c] = 0.0f;

    int nk = K >> 5;

    auto load_tile = [&](int k, int s) {
        int kb = k * 32;
        uint32_t st = stages_u + s * STAGE_B;
        #pragma unroll
        for (int it = 0; it < 2; ++it) {
            int chunk = tid + it * 256;
            int row = chunk >> 2, c8 = chunk & 3;
            uint32_t d = st + row * 80 + c8 * 16;
            long aoff = (long)arow[row] * lda + kb + c8 * 8;
            cpa16(d + AHI_O, Ahi + aoff, 16);
            cpa16(d + ALO_O, Alo + aoff, 16);
            int gn = col0 + row;
            int v = (gn < nB) ? 16 : 0;
            long boff = (long)((gn < nB) ? gn : (nB - 1)) * ldb + kb + c8 * 8;
            cpa16(d + BHI_O, Bhi + boff, v);
            cpa16(d + BLO_O, Blo + boff, v);
        }
        asm volatile("cp.async.commit_group;");
    };

    load_tile(0, 0);
    for (int k = 0; k < nk; ++k) {
        if (k + 1 < nk) {
            load_tile(k + 1, (k + 1) & 1);
            asm volatile("cp.async.wait_group 1;");
        } else {
            asm volatile("cp.async.wait_group 0;");
        }
        __syncthreads();
        uint32_t sbase = stages_u + (k & 1) * STAGE_B;
        #pragma unroll
        for (int k16 = 0; k16 < 2; ++k16) {
            uint32_t ah[2][4], al[2][4];
            #pragma unroll
            for (int mf = 0; mf < 2; ++mf) {
                uint32_t aa = sbase + aOff + mf * 1280 + k16 * 32;
                LDM4(ah[mf], aa);
                LDM4(al[mf], aa + ALO_O);
            }
            #pragma unroll
            for (int n16 = 0; n16 < 4; ++n16) {
                uint32_t bh[4], bl[4];
                uint32_t ba = sbase + bOff + n16 * 1280 + k16 * 32;
                LDM4(bh, ba);
                LDM4(bl, ba + (BLO_O - BHI_O));
                #pragma unroll
                for (int mf = 0; mf < 2; ++mf) {
                    MMA(acc[mf][n16 * 2 + 0], ah[mf], bh[0], bh[2]);
                    MMA(acc[mf][n16 * 2 + 1], ah[mf], bh[1], bh[3]);
                    MMA(acc[mf][n16 * 2 + 0], ah[mf], bl[0], bl[2]);
                    MMA(acc[mf][n16 * 2 + 1], ah[mf], bl[1], bl[3]);
                    MMA(acc[mf][n16 * 2 + 0], al[mf], bh[0], bh[2]);
                    MMA(acc[mf][n16 * 2 + 1], al[mf], bh[1], bh[3]);
                }
            }
        }
        __syncthreads();
    }

    // epilogue straight from registers
    int quad = lane >> 2, ql = lane & 3;
    #pragma unroll
    for (int mf = 0; mf < 2; ++mf) {
        #pragma unroll
        for (int h = 0; h < 2; ++h) {
            int li = wm * 32 + mf * 16 + quad + h * 8;
            int r = row0 + li;
            if (r >= M) continue;
            int tk = tokS[li];
            float w = wS[li];
            #pragma unroll
            for (int n8 = 0; n8 < 8; ++n8) {
                int cc = col0 + wn * 64 + n8 * 8 + ql * 2;
                float v0 = acc[mf][n8][h * 2 + 0];
                float v1 = acc[mf][n8][h * 2 + 1];
                if (mode == 0) {
                    *(float2*)&C[(long)r * ldc + cc] = make_float2(v0, v1);
                } else if (mode == 1) {
                    const float2 b2 = *(const float2*)&base[(long)tk * ldbase + cc];
                    *(float2*)&C[(long)r * ldc + cc] =
                        make_float2(b2.x + v0, b2.y + v1);
                } else if (mode == 2) {
                    float2* o = (float2*)&C[(long)tk * ldc + cc];
                    float2 cur = *o;
                    cur.x += w * v0; cur.y += w * v1;
                    *o = cur;
                } else {
                    unsigned short h0, l0, h1, l1;
                    split_bf16(v0, h0, l0);
                    split_bf16(v1, h1, l1);
                    long o = (long)r * ldc + cc;
                    *(ushort2*)&Chi[o] = make_ushort2(h0, h1);
                    *(ushort2*)&Clo[o] = make_ushort2(l0, l1);
                }
            }
        }
    }
}

// ---------------- launch ----------------
extern "C" void kernel_launch(void* const* d_in, const int* in_sizes, int n_in,
                              void* d_out, int out_size) {
    const float* x  = (const float*)d_in[0];
    const float* wr = (const float*)d_in[1];
    const float* Wg = (const float*)d_in[2];
    const float* Wu = (const float*)d_in[3];
    const float* Wd = (const float*)d_in[4];
    const float* Ag = (const float*)d_in[5];
    const float* Bg = (const float*)d_in[6];
    const float* Au = (const float*)d_in[7];
    const float* Bu = (const float*)d_in[8];
    const float* Ad = (const float*)d_in[9];
    const float* Bd = (const float*)d_in[10];

    float* out = (float*)d_out;
    float* logits_out = out + (long)kT * kH;

    void* p;
#define SYM(var, name) cudaGetSymbolAddress(&p, name); auto* var = (unsigned short*)p;
    SYM(xs_hi, d_xs_hi) SYM(xs_lo, d_xs_lo)
    SYM(wg_hi, d_wg_hi) SYM(wg_lo, d_wg_lo)
    SYM(wu_hi, d_wu_hi) SYM(wu_lo, d_wu_lo)
    SYM(wd_hi, d_wd_hi) SYM(wd_lo, d_wd_lo)
    SYM(ag_hi, d_ag_hi) SYM(ag_lo, d_ag_lo)
    SYM(au_hi, d_au_hi) SYM(au_lo, d_au_lo)
    SYM(bg_hi, d_bg_hi) SYM(bg_lo, d_bg_lo)
    SYM(bu_hi, d_bu_hi) SYM(bu_lo, d_bu_lo)
    SYM(ad_hi, d_ad_hi) SYM(ad_lo, d_ad_lo)
    SYM(bd_hi, d_bd_hi) SYM(bd_lo, d_bd_lo)
    SYM(tg_hi, d_tg_hi) SYM(tg_lo, d_tg_lo)
    SYM(tu_hi, d_tu_hi) SYM(tu_lo, d_tu_lo)
    SYM(td_hi, d_td_hi) SYM(td_lo, d_td_lo)
    SYM(h_hi, d_h_hi)   SYM(h_lo, d_h_lo)
#undef SYM
    cudaGetSymbolAddress(&p, g_base_g);  float* base_g = (float*)p;
    cudaGetSymbolAddress(&p, g_base_u);  float* base_u = (float*)p;
    cudaGetSymbolAddress(&p, g_gbuf);    float* gb = (float*)p;
    cudaGetSymbolAddress(&p, g_ubuf);    float* ub = (float*)p;
    cudaGetSymbolAddress(&p, g_combine); float* combine = (float*)p;
    cudaGetSymbolAddress(&p, g_lists);   int* lists = (int*)p;
    cudaGetSymbolAddress(&p, g_counts);  int* counts = (int*)p;

    cudaFuncSetAttribute(gemm_mma, cudaFuncAttributeMaxDynamicSharedMemorySize, GSMEM);

    init_kernel<<<2048, 256>>>(out);
    router_kernel<<<kT, 256>>>(x, wr, logits_out);

    split_kernel<<<dim3(8, kT), 256>>>(x, kH, xs_hi, xs_lo, kH);
    split_kernel<<<dim3(8, kI), 256>>>(Wg, kH, wg_hi, wg_lo, kH);
    split_kernel<<<dim3(8, kI), 256>>>(Wu, kH, wu_hi, wu_lo, kH);
    split_kernel<<<dim3(4, kH), 256>>>(Wd, kI, wd_hi, wd_lo, kI);
    split_kernel<<<dim3(8, kE * kR), 256>>>(Ag, kH, ag_hi, ag_lo, kH);
    split_kernel<<<dim3(8, kE * kR), 256>>>(Au, kH, au_hi, au_lo, kH);
    split_kernel<<<dim3(3, kE * kI), 256>>>(Bg, kR, bg_hi, bg_lo, kRP);
    split_kernel<<<dim3(3, kE * kI), 256>>>(Bu, kR, bu_hi, bu_lo, kRP);
    split_kernel<<<dim3(4, kE * kR), 256>>>(Ad, kI, ad_hi, ad_lo, kI);
    split_kernel<<<dim3(3, kE * kH), 256>>>(Bd, kR, bd_hi, bd_lo, kRP);

    // base_g = x @ Wg^T, base_u = x @ Wu^T  [8192,1024], K=2048
    gemm_mma<<<dim3(8, 64), 256, GSMEM>>>(
        xs_hi, xs_lo, kH, wg_hi, wg_lo, kH, kI, kH,
        base_g, kI, kT, nullptr, nullptr, 0,
        nullptr, 0, nullptr, 0, nullptr, nullptr, 0);
    gemm_mma<<<dim3(8, 64), 256, GSMEM>>>(
        xs_hi, xs_lo, kH, wu_hi, wu_lo, kH, kI, kH,
        base_u, kI, kT, nullptr, nullptr, 0,
        nullptr, 0, nullptr, 0, nullptr, nullptr, 0);

    for (int e = 0; e < kE; e++) {
        const int* cnt = counts + e;
        const int* lst = lists + (long)e * kT;
        // tg = gather(x) @ Ag_e^T -> bf16 split  [n_e, 640], K=2048
        gemm_mma<<<dim3(5, 64), 256, GSMEM>>>(
            xs_hi, xs_lo, kH,
            ag_hi + (long)e * kR * kH, ag_lo + (long)e * kR * kH, kH, kR, kH,
            nullptr, kRP, kT, cnt, lst, 1,
            nullptr, 0, nullptr, 0, tg_hi, tg_lo, 3);
        gemm_mma<<<dim3(5, 64), 256, GSMEM>>>(
            xs_hi, xs_lo, kH,
            au_hi + (long)e * kR * kH, au_lo + (long)e * kR * kH, kH, kR, kH,
            nullptr, kRP, kT, cnt, lst, 1,
            nullptr, 0, nullptr, 0, tu_hi, tu_lo, 3);
        // g = base_g[tok] + tg @ Bg_e^T  [n_e, 1024], K=640
        gemm_mma<<<dim3(8, 64), 256, GSMEM>>>(
            tg_hi, tg_lo, kRP,
            bg_hi + (long)e * kI * kRP, bg_lo + (long)e * kI * kRP, kRP, kI, kRP,
            gb, kI, kT, cnt, lst, 0,
            base_g, kI, nullptr, 0, nullptr, nullptr, 1);
        gemm_mma<<<dim3(8, 64), 256, GSMEM>>>(
            tu_hi, tu_lo, kRP,
            bu_hi + (long)e * kI * kRP, bu_lo + (long)e * kI * kRP, kRP, kI, kRP,
            ub, kI, kT, cnt, lst, 0,
            base_u, kI, nullptr, 0, nullptr, nullptr, 1);
        // h = silu(g)*u -> bf16 split
        silu_split_kernel<<<4096, 256>>>(gb, ub, h_hi, h_lo, cnt);
        // td = h @ Ad_e^T -> bf16 split  [n_e, 640], K=1024
        gemm_mma<<<dim3(5, 64), 256, GSMEM>>>(
            h_hi, h_lo, kI,
            ad_hi + (long)e * kR * kI, ad_lo + (long)e * kR * kI, kI, kR, kI,
            nullptr, kRP, kT, cnt, nullptr, 0,
            nullptr, 0, nullptr, 0, td_hi, td_lo, 3);
        // out[tok] += c * (h @ Wd^T)  [n_e, 2048], K=1024
        gemm_mma<<<dim3(16, 64), 256, GSMEM>>>(
            h_hi, h_lo, kI, wd_hi, wd_lo, kI, kH, kI,
            out, kH, kT, cnt, lst, 0,
            nullptr, 0, combine, e, nullptr, nullptr, 2);
        // out[tok] += c * (td @ Bd_e^T)  [n_e, 2048], K=640
        gemm_mma<<<dim3(16, 64), 256, GSMEM>>>(
            td_hi, td_lo, kRP,
            bd_hi + (long)e * kH * kRP, bd_lo + (long)e * kH * kRP, kRP, kH, kRP,
            out, kH, kT, cnt, lst, 0,
            nullptr, 0, combine, e, nullptr, nullptr, 2);
    }

    (void)in_sizes; (void)n_in; (void)out_size;
}

// round 5
// speedup vs baseline: 3.3347x; 1.0046x over previous
#include <cuda_runtime.h>
#include <cuda_bf16.h>
#include <cstdint>
#include <math.h>

constexpr int kH = 2048, kI = 1024, kE = 16, kTopK = 8, kR = 602, kT = 8192;
constexpr int kRP = 640;

// ---------------- device scratch ----------------
__device__ __align__(16) unsigned short d_xs_hi[kT * kH];
__device__ __align__(16) unsigned short d_xs_lo[kT * kH];
__device__ __align__(16) unsigned short d_wg_hi[kI * kH];
__device__ __align__(16) unsigned short d_wg_lo[kI * kH];
__device__ __align__(16) unsigned short d_wu_hi[kI * kH];
__device__ __align__(16) unsigned short d_wu_lo[kI * kH];
__device__ __align__(16) unsigned short d_wd_hi[kH * kI];
__device__ __align__(16) unsigned short d_wd_lo[kH * kI];
__device__ __align__(16) unsigned short d_ag_hi[kE * kR * kH];
__device__ __align__(16) unsigned short d_ag_lo[kE * kR * kH];
__device__ __align__(16) unsigned short d_au_hi[kE * kR * kH];
__device__ __align__(16) unsigned short d_au_lo[kE * kR * kH];
__device__ __align__(16) unsigned short d_bg_hi[kE * kI * kRP];
__device__ __align__(16) unsigned short d_bg_lo[kE * kI * kRP];
__device__ __align__(16) unsigned short d_bu_hi[kE * kI * kRP];
__device__ __align__(16) unsigned short d_bu_lo[kE * kI * kRP];
__device__ __align__(16) unsigned short d_ad_hi[kE * kR * kI];
__device__ __align__(16) unsigned short d_ad_lo[kE * kR * kI];
__device__ __align__(16) unsigned short d_bd_hi[kE * kH * kRP];
__device__ __align__(16) unsigned short d_bd_lo[kE * kH * kRP];
__device__ __align__(16) unsigned short d_tgu_hi[kT * 2 * kRP];
__device__ __align__(16) unsigned short d_tgu_lo[kT * 2 * kRP];
__device__ __align__(16) unsigned short d_td_hi[kT * kRP];
__device__ __align__(16) unsigned short d_td_lo[kT * kRP];
__device__ __align__(16) unsigned short d_h_hi[kT * kI];
__device__ __align__(16) unsigned short d_h_lo[kT * kI];
__device__ float g_base_g[kT * kI];
__device__ float g_base_u[kT * kI];
__device__ float g_gbuf[kT * kI];
__device__ float g_ubuf[kT * kI];
__device__ float g_combine[kT * kE];
__device__ int   g_lists[kE * kT];
__device__ int   g_counts[kE];

// ---------------- helpers ----------------
__device__ __forceinline__ uint32_t smem_u32(const void* p) {
    uint32_t a;
    asm("{ .reg .u64 t; cvta.to.shared.u64 t, %1; cvt.u32.u64 %0, t; }"
        : "=r"(a) : "l"(p));
    return a;
}
__device__ __forceinline__ void split_bf16(float v, unsigned short& h, unsigned short& l) {
    __nv_bfloat16 bh = __float2bfloat16(v);
    float r = v - __bfloat162float(bh);
    __nv_bfloat16 bl = __float2bfloat16(r);
    h = __bfloat16_as_ushort(bh);
    l = __bfloat16_as_ushort(bl);
}

#define LDM4(r, a)                                                            \
    asm volatile("ldmatrix.sync.aligned.m8n8.x4.shared.b16 {%0,%1,%2,%3}, [%4];" \
                 : "=r"((r)[0]), "=r"((r)[1]), "=r"((r)[2]), "=r"((r)[3])     \
                 : "r"(a))

#define MMA(c, a, b0, b1)                                                     \
    asm volatile("mma.sync.aligned.m16n8k16.row.col.f32.bf16.bf16.f32 "       \
                 "{%0,%1,%2,%3},{%4,%5,%6,%7},{%8,%9},{%0,%1,%2,%3};"         \
                 : "+f"((c)[0]), "+f"((c)[1]), "+f"((c)[2]), "+f"((c)[3])     \
                 : "r"((a)[0]), "r"((a)[1]), "r"((a)[2]), "r"((a)[3]),        \
                   "r"(b0), "r"(b1))

__device__ __forceinline__ void cpa16(uint32_t dst, const void* src, int sz) {
    asm volatile("cp.async.cg.shared.global [%0], [%1], 16, %2;"
                 :: "r"(dst), "l"(src), "r"(sz));
}

// ---------------- init ----------------
__global__ void init_kernel(float* __restrict__ out) {
    long idx = (long)blockIdx.x * blockDim.x + threadIdx.x;
    long stride = (long)gridDim.x * blockDim.x;
    long total = (long)kT * kH;
    for (long i = idx; i < total; i += stride) out[i] = 0.0f;
    if (idx < kE) g_counts[idx] = 0;
}

// ---------------- router ----------------
__global__ void router_kernel(const float* __restrict__ x,
                              const float* __restrict__ wr,
                              float* __restrict__ logits_out) {
    int t = blockIdx.x;
    __shared__ float xs[kH];
    __shared__ float lg[kE];
    int tid = threadIdx.x;
    for (int i = tid; i < kH; i += 256) xs[i] = x[(long)t * kH + i];
    __syncthreads();
    int w = tid >> 5, lane = tid & 31;
    #pragma unroll
    for (int eo = 0; eo < 2; eo++) {
        int e = w * 2 + eo;
        const float* wre = wr + (long)e * kH;
        float s = 0.0f;
        for (int i = lane; i < kH; i += 32) s += xs[i] * wre[i];
        #pragma unroll
        for (int o = 16; o; o >>= 1) s += __shfl_xor_sync(0xffffffff, s, o);
        if (lane == 0) lg[e] = s;
    }
    __syncthreads();
    if (tid == 0) {
        float mx = lg[0];
        for (int e = 1; e < kE; e++) mx = fmaxf(mx, lg[e]);
        float p[kE]; float sum = 0.0f;
        for (int e = 0; e < kE; e++) { p[e] = expf(lg[e] - mx); sum += p[e]; }
        float inv = 1.0f / sum;
        for (int e = 0; e < kE; e++) p[e] *= inv;
        bool used[kE];
        for (int e = 0; e < kE; e++) used[e] = false;
        int sel[kTopK]; float tsum = 0.0f;
        for (int k = 0; k < kTopK; k++) {
            int bi = -1; float bv = -1.0f;
            for (int e = 0; e < kE; e++)
                if (!used[e] && p[e] > bv) { bv = p[e]; bi = e; }
            used[bi] = true; sel[k] = bi; tsum += bv;
        }
        float itn = 1.0f / tsum;
        for (int e = 0; e < kE; e++)
            g_combine[t * kE + e] = used[e] ? p[e] * itn : 0.0f;
        for (int k = 0; k < kTopK; k++) {
            int e = sel[k];
            int pos = atomicAdd(&g_counts[e], 1);
            g_lists[e * kT + pos] = t;
        }
    }
    if (tid < kE) logits_out[t * kE + tid] = lg[tid];
}

// ---------------- split fp32 -> bf16 hi/lo (pads cols srcLd..dstLd) ---------
__global__ void split_kernel(const float* __restrict__ src, int srcLd,
                             unsigned short* __restrict__ hi,
                             unsigned short* __restrict__ lo, int dstLd) {
    int col = blockIdx.x * 256 + threadIdx.x;
    long row = blockIdx.y;
    if (col >= dstLd) return;
    float v = (col < srcLd) ? src[row * srcLd + col] : 0.0f;
    unsigned short h, l;
    split_bf16(v, h, l);
    long o = row * dstLd + col;
    hi[o] = h; lo[o] = l;
}

// ---------------- h = silu(g)*u -> bf16 split ----------------
__global__ void silu_split_kernel(const float* __restrict__ g,
                                  const float* __restrict__ u,
                                  unsigned short* __restrict__ hhi,
                                  unsigned short* __restrict__ hlo,
                                  const int* __restrict__ cnt) {
    int M = *cnt;
    long total = (long)M * kI;
    long idx = (long)blockIdx.x * blockDim.x + threadIdx.x;
    long stride = (long)gridDim.x * blockDim.x;
    for (long i = idx; i < total; i += stride) {
        float gv = g[i], uv = u[i];
        float hv = gv / (1.0f + expf(-gv)) * uv;
        unsigned short h, l;
        split_bf16(hv, h, l);
        hhi[i] = h; hlo[i] = l;
    }
}

// ---------------- mma.sync bf16 GEMM, 3-term split, CTA 256x128 ------------
// A: optional K-region split at kSplit (A1 then A2).
// B: K-region split at kSplit (B -> Bk2), or N-row split at nSplit (B -> Bn2).
// mode 0: C=acc ; 1: C=base[tok]+acc ; 2: C[tok]+=w*acc ; 3: split->Ch/Cl
struct GArgs {
    const unsigned short *A1h, *A1l; int lda1;
    const unsigned short *A2h, *A2l; int lda2; int kSplit;
    const unsigned short *Bh, *Bl;   int ldb;  int nBv;
    const unsigned short *Bn2h, *Bn2l; int nSplit; int nBn2v;
    const unsigned short *Bk2h, *Bk2l; int ldbk2;
    int K;
    float* C; int ldc;
    int M_static; const int* countPtr; const int* list; int gatherA;
    const float* base; int ldbase;
    const float* combine; int expert;
    unsigned short *Ch, *Cl;
    int mode;
};

constexpr int STAGE_B = 61440;  // Ahi 20480 + Alo 20480 + Bhi 10240 + Blo 10240
constexpr int ALO_O = 20480, BHI_O = 40960;
constexpr int GSMEM = 3072 + 3 * STAGE_B;  // 187392

__global__ __launch_bounds__(512, 1) void gemm_mma(GArgs g) {
    int M = g.countPtr ? *g.countPtr : g.M_static;
    int row0 = blockIdx.y * 256;
    if (row0 >= M) return;
    int col0 = blockIdx.x * 128;

    extern __shared__ char sm[];
    int*   arow = (int*)sm;
    int*   tokS = (int*)(sm + 1024);
    float* wS   = (float*)(sm + 2048);
    uint32_t stages_u = smem_u32(sm + 3072);

    int tid = threadIdx.x;
    int lane = tid & 31, wid = tid >> 5;
    int wm = wid & 7, wn = wid >> 3;

    for (int i = tid; i < 256; i += 512) {
        int r = row0 + i;
        int rr = (r < M) ? r : (M - 1);
        int tk = g.list ? g.list[rr] : rr;
        tokS[i] = tk;
        arow[i] = g.gatherA ? tk : rr;
        wS[i] = (g.mode == 2) ? g.combine[tk * kE + g.expert] : 0.0f;
    }
    __syncthreads();

    const uint32_t aOff = (uint32_t)((wm * 32 + (lane & 15)) * 80 + (lane >> 4) * 16);
    const uint32_t bOff = (uint32_t)(BHI_O + (wn * 64 + (lane & 15)) * 80 + (lane >> 4) * 16);

    float acc[2][8][4];
    #pragma unroll
    for (int a = 0; a < 2; a++)
        #pragma unroll
        for (int b = 0; b < 8; b++)
            #pragma unroll
            for (int c = 0; c < 4; c++) acc[a][b][c] = 0.0f;

    int nk = g.K >> 5;

    auto load_tile = [&](int k) {
        int s = k % 3;
        int kb = k * 32;
        uint32_t st = stages_u + s * STAGE_B;
        bool reg2 = kb >= g.kSplit;
        const unsigned short* pAh = reg2 ? g.A2h : g.A1h;
        const unsigned short* pAl = reg2 ? g.A2l : g.A1l;
        int la = reg2 ? g.lda2 : g.lda1;
        int kk = reg2 ? kb - g.kSplit : kb;
        #pragma unroll
        for (int it = 0; it < 2; ++it) {
            int id = tid + it * 512;
            int row = id >> 2, c8 = id & 3;
            uint32_t d = st + row * 80 + c8 * 16;
            long off = (long)arow[row] * la + kk + c8 * 8;
            cpa16(d, pAh + off, 16);
            cpa16(d + ALO_O, pAl + off, 16);
        }
        {
            int row = tid >> 2, c8 = tid & 3;
            int gn = col0 + row;
            const unsigned short *ph, *pl;
            int lb, rr, vld;
            if (reg2)                { ph = g.Bk2h; pl = g.Bk2l; lb = g.ldbk2; rr = gn;            vld = gn < g.nBv; }
            else if (gn >= g.nSplit) { ph = g.Bn2h; pl = g.Bn2l; lb = g.ldb;   rr = gn - g.nSplit; vld = rr < g.nBn2v; }
            else                     { ph = g.Bh;   pl = g.Bl;   lb = g.ldb;   rr = gn;            vld = gn < g.nBv; }
            if (!vld) rr = 0;
            long off = (long)rr * lb + kk + c8 * 8;
            uint32_t d = st + BHI_O + row * 80 + c8 * 16;
            cpa16(d, ph + off, vld ? 16 : 0);
            cpa16(d + 10240, pl + off, vld ? 16 : 0);
        }
        asm volatile("cp.async.commit_group;");
    };

    load_tile(0);
    load_tile(1);
    for (int k = 0; k < nk; ++k) {
        asm volatile("cp.async.wait_group 1;");
        __syncthreads();
        uint32_t sbase = stages_u + (k % 3) * STAGE_B;
        #pragma unroll
        for (int k16 = 0; k16 < 2; ++k16) {
            uint32_t ah[2][4], al[2][4];
            #pragma unroll
            for (int mf = 0; mf < 2; ++mf) {
                uint32_t aa = sbase + aOff + mf * 1280 + k16 * 32;
                LDM4(ah[mf], aa);
                LDM4(al[mf], aa + ALO_O);
            }
            #pragma unroll
            for (int n16 = 0; n16 < 4; ++n16) {
                uint32_t bh[4], bl[4];
                uint32_t ba = sbase + bOff + n16 * 1280 + k16 * 32;
                LDM4(bh, ba);
                LDM4(bl, ba + 10240);
                #pragma unroll
                for (int mf = 0; mf < 2; ++mf) {
                    MMA(acc[mf][n16 * 2 + 0], ah[mf], bh[0], bh[2]);
                    MMA(acc[mf][n16 * 2 + 1], ah[mf], bh[1], bh[3]);
                    MMA(acc[mf][n16 * 2 + 0], ah[mf], bl[0], bl[2]);
                    MMA(acc[mf][n16 * 2 + 1], ah[mf], bl[1], bl[3]);
                    MMA(acc[mf][n16 * 2 + 0], al[mf], bh[0], bh[2]);
                    MMA(acc[mf][n16 * 2 + 1], al[mf], bh[1], bh[3]);
                }
            }
        }
        if (k + 2 < nk) load_tile(k + 2);
        else asm volatile("cp.async.commit_group;");
    }

    int quad = lane >> 2, ql = lane & 3;
    #pragma unroll
    for (int mf = 0; mf < 2; ++mf) {
        #pragma unroll
        for (int h = 0; h < 2; ++h) {
            int li = wm * 32 + mf * 16 + quad + h * 8;
            int r = row0 + li;
            if (r >= M) continue;
            int tk = tokS[li];
            float w = wS[li];
            #pragma unroll
            for (int n8 = 0; n8 < 8; ++n8) {
                int cc = col0 + wn * 64 + n8 * 8 + ql * 2;
                float v0 = acc[mf][n8][h * 2 + 0];
                float v1 = acc[mf][n8][h * 2 + 1];
                if (g.mode == 0) {
                    *(float2*)&g.C[(long)r * g.ldc + cc] = make_float2(v0, v1);
                } else if (g.mode == 1) {
                    const float2 b2 = *(const float2*)&g.base[(long)tk * g.ldbase + cc];
                    *(float2*)&g.C[(long)r * g.ldc + cc] = make_float2(b2.x + v0, b2.y + v1);
                } else if (g.mode == 2) {
                    float2* o = (float2*)&g.C[(long)tk * g.ldc + cc];
                    float2 cur = *o;
                    cur.x += w * v0; cur.y += w * v1;
                    *o = cur;
                } else {
                    unsigned short h0, l0, h1, l1;
                    split_bf16(v0, h0, l0);
                    split_bf16(v1, h1, l1);
                    long o = (long)r * g.ldc + cc;
                    *(ushort2*)&g.Ch[o] = make_ushort2(h0, h1);
                    *(ushort2*)&g.Cl[o] = make_ushort2(l0, l1);
                }
            }
        }
    }
}

// ---------------- launch ----------------
extern "C" void kernel_launch(void* const* d_in, const int* in_sizes, int n_in,
                              void* d_out, int out_size) {
    const float* x  = (const float*)d_in[0];
    const float* wr = (const float*)d_in[1];
    const float* Wg = (const float*)d_in[2];
    const float* Wu = (const float*)d_in[3];
    const float* Wd = (const float*)d_in[4];
    const float* Ag = (const float*)d_in[5];
    const float* Bg = (const float*)d_in[6];
    const float* Au = (const float*)d_in[7];
    const float* Bu = (const float*)d_in[8];
    const float* Ad = (const float*)d_in[9];
    const float* Bd = (const float*)d_in[10];

    float* out = (float*)d_out;
    float* logits_out = out + (long)kT * kH;

    void* p;
#define SYM(var, name) cudaGetSymbolAddress(&p, name); auto* var = (unsigned short*)p;
    SYM(xs_hi, d_xs_hi) SYM(xs_lo, d_xs_lo)
    SYM(wg_hi, d_wg_hi) SYM(wg_lo, d_wg_lo)
    SYM(wu_hi, d_wu_hi) SYM(wu_lo, d_wu_lo)
    SYM(wd_hi, d_wd_hi) SYM(wd_lo, d_wd_lo)
    SYM(ag_hi, d_ag_hi) SYM(ag_lo, d_ag_lo)
    SYM(au_hi, d_au_hi) SYM(au_lo, d_au_lo)
    SYM(bg_hi, d_bg_hi) SYM(bg_lo, d_bg_lo)
    SYM(bu_hi, d_bu_hi) SYM(bu_lo, d_bu_lo)
    SYM(ad_hi, d_ad_hi) SYM(ad_lo, d_ad_lo)
    SYM(bd_hi, d_bd_hi) SYM(bd_lo, d_bd_lo)
    SYM(tgu_hi, d_tgu_hi) SYM(tgu_lo, d_tgu_lo)
    SYM(td_hi, d_td_hi) SYM(td_lo, d_td_lo)
    SYM(h_hi, d_h_hi)   SYM(h_lo, d_h_lo)
#undef SYM
    cudaGetSymbolAddress(&p, g_base_g);  float* base_g = (float*)p;
    cudaGetSymbolAddress(&p, g_base_u);  float* base_u = (float*)p;
    cudaGetSymbolAddress(&p, g_gbuf);    float* gb = (float*)p;
    cudaGetSymbolAddress(&p, g_ubuf);    float* ub = (float*)p;
    cudaGetSymbolAddress(&p, g_combine); float* combine = (float*)p;
    cudaGetSymbolAddress(&p, g_lists);   int* lists = (int*)p;
    cudaGetSymbolAddress(&p, g_counts);  int* counts = (int*)p;

    cudaFuncSetAttribute(gemm_mma, cudaFuncAttributeMaxDynamicSharedMemorySize, GSMEM);

    init_kernel<<<2048, 256>>>(out);
    router_kernel<<<kT, 256>>>(x, wr, logits_out);

    split_kernel<<<dim3(8, kT), 256>>>(x, kH, xs_hi, xs_lo, kH);
    split_kernel<<<dim3(8, kI), 256>>>(Wg, kH, wg_hi, wg_lo, kH);
    split_kernel<<<dim3(8, kI), 256>>>(Wu, kH, wu_hi, wu_lo, kH);
    split_kernel<<<dim3(4, kH), 256>>>(Wd, kI, wd_hi, wd_lo, kI);
    split_kernel<<<dim3(8, kE * kR), 256>>>(Ag, kH, ag_hi, ag_lo, kH);
    split_kernel<<<dim3(8, kE * kR), 256>>>(Au, kH, au_hi, au_lo, kH);
    split_kernel<<<dim3(3, kE * kI), 256>>>(Bg, kR, bg_hi, bg_lo, kRP);
    split_kernel<<<dim3(3, kE * kI), 256>>>(Bu, kR, bu_hi, bu_lo, kRP);
    split_kernel<<<dim3(4, kE * kR), 256>>>(Ad, kI, ad_hi, ad_lo, kI);
    split_kernel<<<dim3(3, kE * kH), 256>>>(Bd, kR, bd_hi, bd_lo, kRP);

    auto mkargs = [&]() {
        GArgs a;
        a.A1h = a.A1l = a.A2h = a.A2l = nullptr; a.lda1 = a.lda2 = 0;
        a.kSplit = 1 << 30;
        a.Bh = a.Bl = a.Bn2h = a.Bn2l = a.Bk2h = a.Bk2l = nullptr;
        a.ldb = a.ldbk2 = 0; a.nBv = 0; a.nSplit = 1 << 30; a.nBn2v = 0;
        a.K = 0; a.C = nullptr; a.ldc = 0;
        a.M_static = kT; a.countPtr = nullptr; a.list = nullptr; a.gatherA = 0;
        a.base = nullptr; a.ldbase = 0; a.combine = nullptr; a.expert = 0;
        a.Ch = a.Cl = nullptr; a.mode = 0;
        return a;
    };

    // base_g / base_u: [8192,1024] = x @ W^T, K=2048
    {
        GArgs a = mkargs();
        a.A1h = xs_hi; a.A1l = xs_lo; a.lda1 = kH;
        a.Bh = wg_hi; a.Bl = wg_lo; a.ldb = kH; a.nBv = kI;
        a.K = kH; a.C = base_g; a.ldc = kI; a.mode = 0;
        gemm_mma<<<dim3(8, 32), 512, GSMEM>>>(a);
        a.Bh = wu_hi; a.Bl = wu_lo; a.C = base_u;
        gemm_mma<<<dim3(8, 32), 512, GSMEM>>>(a);
    }

    for (int e = 0; e < kE; e++) {
        const int* cnt = counts + e;
        const int* lst = lists + (long)e * kT;
        // fused tg|tu = gather(x) @ [Ag;Au]^T -> split, [n_e,1280], K=2048
        {
            GArgs a = mkargs();
            a.A1h = xs_hi; a.A1l = xs_lo; a.lda1 = kH;
            a.Bh = ag_hi + (long)e * kR * kH; a.Bl = ag_lo + (long)e * kR * kH;
            a.ldb = kH; a.nBv = kR;
            a.Bn2h = au_hi + (long)e * kR * kH; a.Bn2l = au_lo + (long)e * kR * kH;
            a.nSplit = kRP; a.nBn2v = kR;
            a.K = kH; a.countPtr = cnt; a.list = lst; a.gatherA = 1;
            a.Ch = tgu_hi; a.Cl = tgu_lo; a.ldc = 2 * kRP; a.mode = 3;
            gemm_mma<<<dim3(10, 32), 512, GSMEM>>>(a);
        }
        // g = base_g[tok] + tg @ Bg^T  [n_e,1024], K=640
        {
            GArgs a = mkargs();
            a.A1h = tgu_hi; a.A1l = tgu_lo; a.lda1 = 2 * kRP;
            a.Bh = bg_hi + (long)e * kI * kRP; a.Bl = bg_lo + (long)e * kI * kRP;
            a.ldb = kRP; a.nBv = kI;
            a.K = kRP; a.countPtr = cnt; a.list = lst;
            a.base = base_g; a.ldbase = kI;
            a.C = gb; a.ldc = kI; a.mode = 1;
            gemm_mma<<<dim3(8, 32), 512, GSMEM>>>(a);
            a.A1h = tgu_hi + kRP; a.A1l = tgu_lo + kRP;
            a.Bh = bu_hi + (long)e * kI * kRP; a.Bl = bu_lo + (long)e * kI * kRP;
            a.base = base_u; a.C = ub;
            gemm_mma<<<dim3(8, 32), 512, GSMEM>>>(a);
        }
        silu_split_kernel<<<4096, 256>>>(gb, ub, h_hi, h_lo, cnt);
        // td = h @ Ad^T -> split  [n_e,640], K=1024
        {
            GArgs a = mkargs();
            a.A1h = h_hi; a.A1l = h_lo; a.lda1 = kI;
            a.Bh = ad_hi + (long)e * kR * kI; a.Bl = ad_lo + (long)e * kR * kI;
            a.ldb = kI; a.nBv = kR;
            a.K = kI; a.countPtr = cnt;
            a.Ch = td_hi; a.Cl = td_lo; a.ldc = kRP; a.mode = 3;
            gemm_mma<<<dim3(5, 32), 512, GSMEM>>>(a);
        }
        // out[tok] += c * ([h|td] @ [Wd|Bd]^T)  [n_e,2048], K=1024+640
        {
            GArgs a = mkargs();
            a.A1h = h_hi; a.A1l = h_lo; a.lda1 = kI;
            a.A2h = td_hi; a.A2l = td_lo; a.lda2 = kRP; a.kSplit = kI;
            a.Bh = wd_hi; a.Bl = wd_lo; a.ldb = kI; a.nBv = kH;
            a.Bk2h = bd_hi + (long)e * kH * kRP; a.Bk2l = bd_lo + (long)e * kH * kRP;
            a.ldbk2 = kRP;
            a.K = kI + kRP; a.countPtr = cnt; a.list = lst;
            a.combine = combine; a.expert = e;
            a.C = out; a.ldc = kH; a.mode = 2;
            gemm_mma<<<dim3(16, 32), 512, GSMEM>>>(a);
        }
    }

    (void)in_sizes; (void)n_in; (void)out_size;
}